// round 11
// baseline (speedup 1.0000x reference)
#include <cuda_runtime.h>

// VAE forward, B = 4,000,000 rows. SINGLE kernel: every block writes the
// duplicated (w,w) weight pairs into the __constant__ backing store itself
// (idempotent same-value writes), __threadfence + __syncthreads, then reads
// them via LDCU (uniform port). Deletes the prep-kernel graph node that cost
// 3.5-6.4us of serialized launch overhead in R5-R9.
// Math per chunk unchanged from R9 best: 2 rows/thread packed f32x2, NT=128.
//
// Inputs: x[B,8], eps[B,4], w1[6,8], w21[4,6], w22[4,6], w3[6,4], w4[8,6]
// Output: concat(out[B,8], mu[B,4], logvar[B,4]) float32.

#define NT 128

typedef unsigned long long u64;

// Pair layout (u64 index): W1 [0,48) j*8+k | W21 [48,72) j*6+k | W22 [72,96)
//                          W3 [96,120) j*4+k | W4 [120,168) j*6+k
__constant__ ulonglong2 cw[84];

__device__ __forceinline__ u64 pk(float lo, float hi) {
    u64 d; asm("mov.b64 %0,{%1,%2};" : "=l"(d) : "f"(lo), "f"(hi)); return d;
}
__device__ __forceinline__ void upk(float& lo, float& hi, u64 v) {
    asm("mov.b64 {%0,%1},%2;" : "=f"(lo), "=f"(hi) : "l"(v));
}
__device__ __forceinline__ u64 fma2(u64 a, u64 b, u64 c) {
    u64 d; asm("fma.rn.f32x2 %0,%1,%2,%3;" : "=l"(d) : "l"(a), "l"(b), "l"(c)); return d;
}
__device__ __forceinline__ u64 mul2(u64 a, u64 b) {
    u64 d; asm("mul.rn.f32x2 %0,%1,%2;" : "=l"(d) : "l"(a), "l"(b)); return d;
}
__device__ __forceinline__ u64 elu2(u64 s) {
    float lo, hi; upk(lo, hi, s);
    lo = lo > 0.0f ? lo : (__expf(lo) - 1.0f);
    hi = hi > 0.0f ? hi : (__expf(hi) - 1.0f);
    return pk(lo, hi);
}
// exp(0.5*x) = 2^(x * 0.72134752)
__device__ __forceinline__ float exph(float v) {
    return exp2f(v * 0.72134752044448170368f);
}

__global__ __launch_bounds__(NT)
void vae_kernel(const float4* __restrict__ x,
                const float4* __restrict__ eps,
                const float* __restrict__ w1,
                const float* __restrict__ w21,
                const float* __restrict__ w22,
                const float* __restrict__ w3,
                const float* __restrict__ w4,
                u64* __restrict__ cw_backing,   // == device address of cw
                float4* __restrict__ out,
                float4* __restrict__ mu_out,
                float4* __restrict__ lv_out,
                int B)
{
    const int t  = threadIdx.x;
    const int i0 = blockIdx.x * (2 * NT) + t;
    const int i1 = i0 + NT;
    const bool v1 = i1 < B;
    const bool v0 = i0 < B;

    const float4 z4 = make_float4(0.f, 0.f, 0.f, 0.f);

    // ---- issue input loads FIRST (overlap with the weight-prep prologue) ----
    float4 xa0 = z4, xb0 = z4, e0 = z4, xa1 = z4, xb1 = z4, e1 = z4;
    if (v0) {
        xa0 = __ldcs(&x[2 * i0]);
        xb0 = __ldcs(&x[2 * i0 + 1]);
        e0  = __ldcs(&eps[i0]);
        if (v1) {
            xa1 = __ldcs(&x[2 * i1]);
            xb1 = __ldcs(&x[2 * i1 + 1]);
            e1  = __ldcs(&eps[i1]);
        }
    }

    // ---- weight prep: every block writes identical (w,w) pairs into cw's
    //      backing store. Idempotent across blocks; fence+bar orders the
    //      block's own writes before its first constant-cache fill. ----
#pragma unroll
    for (int e = t; e < 168; e += NT) {
        float w;
        if (e < 48)       w = w1[e];
        else if (e < 72)  w = w21[e - 48];
        else if (e < 96)  w = w22[e - 72];
        else if (e < 120) w = w3[e - 96];
        else              w = w4[e - 120];
        cw_backing[e] = pk(w, w);
    }
    __threadfence();
    __syncthreads();

    if (!v0) return;

    u64 X[8];
    X[0] = pk(xa0.x, xa1.x); X[1] = pk(xa0.y, xa1.y);
    X[2] = pk(xa0.z, xa1.z); X[3] = pk(xa0.w, xa1.w);
    X[4] = pk(xb0.x, xb1.x); X[5] = pk(xb0.y, xb1.y);
    X[6] = pk(xb0.z, xb1.z); X[7] = pk(xb0.w, xb1.w);
    u64 E[4];
    E[0] = pk(e0.x, e1.x); E[1] = pk(e0.y, e1.y);
    E[2] = pk(e0.z, e1.z); E[3] = pk(e0.w, e1.w);

    // ---- encoder: h1 = elu(x @ w1.T); weights via LDCU (uniform port) ----
    u64 h1[6];
#pragma unroll
    for (int j = 0; j < 6; j++) {
        const ulonglong2 p0 = cw[j * 4 + 0];
        const ulonglong2 p1 = cw[j * 4 + 1];
        const ulonglong2 p2 = cw[j * 4 + 2];
        const ulonglong2 p3 = cw[j * 4 + 3];
        u64 s = mul2(X[0], p0.x);
        s = fma2(X[1], p0.y, s);
        s = fma2(X[2], p1.x, s);
        s = fma2(X[3], p1.y, s);
        s = fma2(X[4], p2.x, s);
        s = fma2(X[5], p2.y, s);
        s = fma2(X[6], p3.x, s);
        s = fma2(X[7], p3.y, s);
        h1[j] = elu2(s);
    }

    // ---- mu / logvar ----
    u64 mu[4], lv[4];
#pragma unroll
    for (int j = 0; j < 4; j++) {
        const ulonglong2 m0 = cw[24 + j * 3 + 0];
        const ulonglong2 m1 = cw[24 + j * 3 + 1];
        const ulonglong2 m2 = cw[24 + j * 3 + 2];
        u64 sm = mul2(h1[0], m0.x);
        sm = fma2(h1[1], m0.y, sm);
        sm = fma2(h1[2], m1.x, sm);
        sm = fma2(h1[3], m1.y, sm);
        sm = fma2(h1[4], m2.x, sm);
        sm = fma2(h1[5], m2.y, sm);
        mu[j] = sm;
        const ulonglong2 l0 = cw[36 + j * 3 + 0];
        const ulonglong2 l1 = cw[36 + j * 3 + 1];
        const ulonglong2 l2 = cw[36 + j * 3 + 2];
        u64 sl = mul2(h1[0], l0.x);
        sl = fma2(h1[1], l0.y, sl);
        sl = fma2(h1[2], l1.x, sl);
        sl = fma2(h1[3], l1.y, sl);
        sl = fma2(h1[4], l2.x, sl);
        sl = fma2(h1[5], l2.y, sl);
        lv[j] = sl;
    }

    // ---- unpack mu/lv, store, reparameterize ----
    float m0a, m0b, m1a, m1b, m2a, m2b, m3a, m3b;
    upk(m0a, m0b, mu[0]); upk(m1a, m1b, mu[1]);
    upk(m2a, m2b, mu[2]); upk(m3a, m3b, mu[3]);
    float l0a, l0b, l1a, l1b, l2a, l2b, l3a, l3b;
    upk(l0a, l0b, lv[0]); upk(l1a, l1b, lv[1]);
    upk(l2a, l2b, lv[2]); upk(l3a, l3b, lv[3]);

    __stcs(&mu_out[i0], make_float4(m0a, m1a, m2a, m3a));
    __stcs(&lv_out[i0], make_float4(l0a, l1a, l2a, l3a));
    if (v1) {
        __stcs(&mu_out[i1], make_float4(m0b, m1b, m2b, m3b));
        __stcs(&lv_out[i1], make_float4(l0b, l1b, l2b, l3b));
    }

    u64 z[4];
    z[0] = fma2(E[0], pk(exph(l0a), exph(l0b)), mu[0]);
    z[1] = fma2(E[1], pk(exph(l1a), exph(l1b)), mu[1]);
    z[2] = fma2(E[2], pk(exph(l2a), exph(l2b)), mu[2]);
    z[3] = fma2(E[3], pk(exph(l3a), exph(l3b)), mu[3]);

    // ---- decoder: h3 = elu(z @ w3.T) ----
    u64 h3[6];
#pragma unroll
    for (int j = 0; j < 6; j++) {
        const ulonglong2 p0 = cw[48 + j * 2 + 0];
        const ulonglong2 p1 = cw[48 + j * 2 + 1];
        u64 s = mul2(z[0], p0.x);
        s = fma2(z[1], p0.y, s);
        s = fma2(z[2], p1.x, s);
        s = fma2(z[3], p1.y, s);
        h3[j] = elu2(s);
    }

    // ---- out = h3 @ w4.T ----
    float oa[8], ob[8];
#pragma unroll
    for (int j = 0; j < 8; j++) {
        const ulonglong2 p0 = cw[60 + j * 3 + 0];
        const ulonglong2 p1 = cw[60 + j * 3 + 1];
        const ulonglong2 p2 = cw[60 + j * 3 + 2];
        u64 s = mul2(h3[0], p0.x);
        s = fma2(h3[1], p0.y, s);
        s = fma2(h3[2], p1.x, s);
        s = fma2(h3[3], p1.y, s);
        s = fma2(h3[4], p2.x, s);
        s = fma2(h3[5], p2.y, s);
        upk(oa[j], ob[j], s);
    }

    __stcs(&out[2 * i0],     make_float4(oa[0], oa[1], oa[2], oa[3]));
    __stcs(&out[2 * i0 + 1], make_float4(oa[4], oa[5], oa[6], oa[7]));
    if (v1) {
        __stcs(&out[2 * i1],     make_float4(ob[0], ob[1], ob[2], ob[3]));
        __stcs(&out[2 * i1 + 1], make_float4(ob[4], ob[5], ob[6], ob[7]));
    }
}

extern "C" void kernel_launch(void* const* d_in, const int* in_sizes, int n_in,
                              void* d_out, int out_size)
{
    const float4* x   = (const float4*)d_in[0];
    const float4* eps = (const float4*)d_in[1];
    const float*  w1  = (const float*)d_in[2];
    const float*  w21 = (const float*)d_in[3];
    const float*  w22 = (const float*)d_in[4];
    const float*  w3  = (const float*)d_in[5];
    const float*  w4  = (const float*)d_in[6];

    const int B = in_sizes[0] / 8;

    float* outf = (float*)d_out;
    float4* out    = (float4*)outf;
    float4* mu_out = (float4*)(outf + (size_t)B * 8);
    float4* lv_out = (float4*)(outf + (size_t)B * 12);

    void* cw_ptr = nullptr;
    cudaGetSymbolAddress(&cw_ptr, cw);

    const int rows_per_block = 2 * NT;
    const int grid = (B + rows_per_block - 1) / rows_per_block;
    vae_kernel<<<grid, NT>>>(x, eps, w1, w21, w22, w3, w4,
                             (u64*)cw_ptr, out, mu_out, lv_out, B);
}

// round 12
// speedup vs baseline: 2.3665x; 2.3665x over previous
#include <cuda_runtime.h>

// VAE forward, B = 4,000,000 rows. Single kernel (1 graph node, ~1.3us
// overhead vs 3.5-6.4us for the two-kernel LDCU structure). Weights staged
// per-block into shared memory as duplicated (w,w) pairs; math is the proven
// f32x2 row-packed form (2 rows/thread), NT=128, exp(0.5x)=exp2(0.7213x).
// R11 lesson: never have all blocks write one global region (L2 serialization).
//
// Inputs: x[B,8], eps[B,4], w1[6,8], w21[4,6], w22[4,6], w3[6,4], w4[8,6]
// Output: concat(out[B,8], mu[B,4], logvar[B,4]) float32.

#define NT 128

typedef unsigned long long u64;

__device__ __forceinline__ u64 pk(float lo, float hi) {
    u64 d; asm("mov.b64 %0,{%1,%2};" : "=l"(d) : "f"(lo), "f"(hi)); return d;
}
__device__ __forceinline__ void upk(float& lo, float& hi, u64 v) {
    asm("mov.b64 {%0,%1},%2;" : "=f"(lo), "=f"(hi) : "l"(v));
}
__device__ __forceinline__ u64 fma2(u64 a, u64 b, u64 c) {
    u64 d; asm("fma.rn.f32x2 %0,%1,%2,%3;" : "=l"(d) : "l"(a), "l"(b), "l"(c)); return d;
}
__device__ __forceinline__ u64 mul2(u64 a, u64 b) {
    u64 d; asm("mul.rn.f32x2 %0,%1,%2;" : "=l"(d) : "l"(a), "l"(b)); return d;
}
__device__ __forceinline__ u64 elu2(u64 s) {
    float lo, hi; upk(lo, hi, s);
    lo = lo > 0.0f ? lo : (__expf(lo) - 1.0f);
    hi = hi > 0.0f ? hi : (__expf(hi) - 1.0f);
    return pk(lo, hi);
}
// exp(0.5*x) = 2^(x * 0.72134752)
__device__ __forceinline__ float exph(float v) {
    return exp2f(v * 0.72134752044448170368f);
}

// Shared dup-pair layout (pair index): W1 [0,48) j*8+k | W21 [48,72) j*6+k |
// W22 [72,96) | W3 [96,120) j*4+k | W4 [120,168) j*6+k.
// ulonglong2 index = pair/2; every matrix row starts at an even pair.

__global__ __launch_bounds__(NT)
void vae_kernel(const float4* __restrict__ x,
                const float4* __restrict__ eps,
                const float* __restrict__ w1,
                const float* __restrict__ w21,
                const float* __restrict__ w22,
                const float* __restrict__ w3,
                const float* __restrict__ w4,
                float4* __restrict__ out,
                float4* __restrict__ mu_out,
                float4* __restrict__ lv_out,
                int B)
{
    __shared__ ulonglong2 sd[84];

    const int t  = threadIdx.x;
    const int i0 = blockIdx.x * (2 * NT) + t;
    const int i1 = i0 + NT;
    const bool v0 = i0 < B;
    const bool v1 = i1 < B;

    const float4 z4 = make_float4(0.f, 0.f, 0.f, 0.f);

    // ---- issue input loads FIRST (overlap DRAM latency with smem prologue) ----
    float4 xa0 = z4, xb0 = z4, e0 = z4, xa1 = z4, xb1 = z4, e1 = z4;
    if (v0) {
        xa0 = __ldcs(&x[2 * i0]);
        xb0 = __ldcs(&x[2 * i0 + 1]);
        e0  = __ldcs(&eps[i0]);
        if (v1) {
            xa1 = __ldcs(&x[2 * i1]);
            xb1 = __ldcs(&x[2 * i1 + 1]);
            e1  = __ldcs(&eps[i1]);
        }
    }

    // ---- stage duplicated (w,w) pairs into shared ----
    {
        float* sf = (float*)sd;
#pragma unroll
        for (int e = t; e < 168; e += NT) {
            float w;
            if (e < 48)       w = w1[e];
            else if (e < 72)  w = w21[e - 48];
            else if (e < 96)  w = w22[e - 72];
            else if (e < 120) w = w3[e - 96];
            else              w = w4[e - 120];
            sf[2 * e]     = w;
            sf[2 * e + 1] = w;
        }
    }
    __syncthreads();

    if (!v0) return;

    u64 X[8];
    X[0] = pk(xa0.x, xa1.x); X[1] = pk(xa0.y, xa1.y);
    X[2] = pk(xa0.z, xa1.z); X[3] = pk(xa0.w, xa1.w);
    X[4] = pk(xb0.x, xb1.x); X[5] = pk(xb0.y, xb1.y);
    X[6] = pk(xb0.z, xb1.z); X[7] = pk(xb0.w, xb1.w);
    u64 E[4];
    E[0] = pk(e0.x, e1.x); E[1] = pk(e0.y, e1.y);
    E[2] = pk(e0.z, e1.z); E[3] = pk(e0.w, e1.w);

    // ---- encoder: h1 = elu(x @ w1.T); row j = 4 LDS.128 ----
    u64 h1[6];
#pragma unroll
    for (int j = 0; j < 6; j++) {
        const ulonglong2 p0 = sd[j * 4 + 0];
        const ulonglong2 p1 = sd[j * 4 + 1];
        const ulonglong2 p2 = sd[j * 4 + 2];
        const ulonglong2 p3 = sd[j * 4 + 3];
        u64 s = mul2(X[0], p0.x);
        s = fma2(X[1], p0.y, s);
        s = fma2(X[2], p1.x, s);
        s = fma2(X[3], p1.y, s);
        s = fma2(X[4], p2.x, s);
        s = fma2(X[5], p2.y, s);
        s = fma2(X[6], p3.x, s);
        s = fma2(X[7], p3.y, s);
        h1[j] = elu2(s);
    }

    // ---- mu / logvar: rows of 6 pairs = 3 LDS.128 each ----
    u64 mu[4], lv[4];
#pragma unroll
    for (int j = 0; j < 4; j++) {
        const ulonglong2 m0 = sd[24 + j * 3 + 0];
        const ulonglong2 m1 = sd[24 + j * 3 + 1];
        const ulonglong2 m2 = sd[24 + j * 3 + 2];
        u64 sm = mul2(h1[0], m0.x);
        sm = fma2(h1[1], m0.y, sm);
        sm = fma2(h1[2], m1.x, sm);
        sm = fma2(h1[3], m1.y, sm);
        sm = fma2(h1[4], m2.x, sm);
        sm = fma2(h1[5], m2.y, sm);
        mu[j] = sm;
        const ulonglong2 l0 = sd[36 + j * 3 + 0];
        const ulonglong2 l1 = sd[36 + j * 3 + 1];
        const ulonglong2 l2 = sd[36 + j * 3 + 2];
        u64 sl = mul2(h1[0], l0.x);
        sl = fma2(h1[1], l0.y, sl);
        sl = fma2(h1[2], l1.x, sl);
        sl = fma2(h1[3], l1.y, sl);
        sl = fma2(h1[4], l2.x, sl);
        sl = fma2(h1[5], l2.y, sl);
        lv[j] = sl;
    }

    // ---- unpack mu/lv, store, reparameterize ----
    float m0a, m0b, m1a, m1b, m2a, m2b, m3a, m3b;
    upk(m0a, m0b, mu[0]); upk(m1a, m1b, mu[1]);
    upk(m2a, m2b, mu[2]); upk(m3a, m3b, mu[3]);
    float l0a, l0b, l1a, l1b, l2a, l2b, l3a, l3b;
    upk(l0a, l0b, lv[0]); upk(l1a, l1b, lv[1]);
    upk(l2a, l2b, lv[2]); upk(l3a, l3b, lv[3]);

    __stcs(&mu_out[i0], make_float4(m0a, m1a, m2a, m3a));
    __stcs(&lv_out[i0], make_float4(l0a, l1a, l2a, l3a));
    if (v1) {
        __stcs(&mu_out[i1], make_float4(m0b, m1b, m2b, m3b));
        __stcs(&lv_out[i1], make_float4(l0b, l1b, l2b, l3b));
    }

    u64 z[4];
    z[0] = fma2(E[0], pk(exph(l0a), exph(l0b)), mu[0]);
    z[1] = fma2(E[1], pk(exph(l1a), exph(l1b)), mu[1]);
    z[2] = fma2(E[2], pk(exph(l2a), exph(l2b)), mu[2]);
    z[3] = fma2(E[3], pk(exph(l3a), exph(l3b)), mu[3]);

    // ---- decoder: h3 = elu(z @ w3.T); rows of 4 pairs = 2 LDS.128 ----
    u64 h3[6];
#pragma unroll
    for (int j = 0; j < 6; j++) {
        const ulonglong2 p0 = sd[48 + j * 2 + 0];
        const ulonglong2 p1 = sd[48 + j * 2 + 1];
        u64 s = mul2(z[0], p0.x);
        s = fma2(z[1], p0.y, s);
        s = fma2(z[2], p1.x, s);
        s = fma2(z[3], p1.y, s);
        h3[j] = elu2(s);
    }

    // ---- out = h3 @ w4.T; rows of 6 pairs = 3 LDS.128 ----
    float oa[8], ob[8];
#pragma unroll
    for (int j = 0; j < 8; j++) {
        const ulonglong2 p0 = sd[60 + j * 3 + 0];
        const ulonglong2 p1 = sd[60 + j * 3 + 1];
        const ulonglong2 p2 = sd[60 + j * 3 + 2];
        u64 s = mul2(h3[0], p0.x);
        s = fma2(h3[1], p0.y, s);
        s = fma2(h3[2], p1.x, s);
        s = fma2(h3[3], p1.y, s);
        s = fma2(h3[4], p2.x, s);
        s = fma2(h3[5], p2.y, s);
        upk(oa[j], ob[j], s);
    }

    __stcs(&out[2 * i0],     make_float4(oa[0], oa[1], oa[2], oa[3]));
    __stcs(&out[2 * i0 + 1], make_float4(oa[4], oa[5], oa[6], oa[7]));
    if (v1) {
        __stcs(&out[2 * i1],     make_float4(ob[0], ob[1], ob[2], ob[3]));
        __stcs(&out[2 * i1 + 1], make_float4(ob[4], ob[5], ob[6], ob[7]));
    }
}

extern "C" void kernel_launch(void* const* d_in, const int* in_sizes, int n_in,
                              void* d_out, int out_size)
{
    const float4* x   = (const float4*)d_in[0];
    const float4* eps = (const float4*)d_in[1];
    const float*  w1  = (const float*)d_in[2];
    const float*  w21 = (const float*)d_in[3];
    const float*  w22 = (const float*)d_in[4];
    const float*  w3  = (const float*)d_in[5];
    const float*  w4  = (const float*)d_in[6];

    const int B = in_sizes[0] / 8;

    float* outf = (float*)d_out;
    float4* out    = (float4*)outf;
    float4* mu_out = (float4*)(outf + (size_t)B * 8);
    float4* lv_out = (float4*)(outf + (size_t)B * 12);

    const int rows_per_block = 2 * NT;
    const int grid = (B + rows_per_block - 1) / rows_per_block;
    vae_kernel<<<grid, NT>>>(x, eps, w1, w21, w22, w3, w4,
                             out, mu_out, lv_out, B);
}

// round 13
// speedup vs baseline: 2.3817x; 1.0064x over previous
#include <cuda_runtime.h>

// VAE forward, B = 4,000,000 rows. Single kernel, NT=128, 2 rows/thread.
// NEURON-PAIR f32x2 packing: each 64-bit lane pair holds two OUTPUT NEURONS
// (j, j+1) of one row, so weight pairs (w[j][k], w[j+1][k]) are stored in
// shared WITHOUT duplication and each weight register feeds both rows:
// 84 -> 42 LDS.128 per thread (halves the binding L1 traffic of R12).
// Activation operands are dup pairs (v,v) built by mov.b64 {r,r} (CSE-able).
// Epilogue is free: mu/lv/out pairs are row-major -> st.global.cs.v2.u64.
//
// Inputs: x[B,8], eps[B,4], w1[6,8], w21[4,6], w22[4,6], w3[6,4], w4[8,6]
// Output: concat(out[B,8], mu[B,4], logvar[B,4]) float32.

#define NT 128

typedef unsigned long long u64;

__device__ __forceinline__ u64 pk(float lo, float hi) {
    u64 d; asm("mov.b64 %0,{%1,%2};" : "=l"(d) : "f"(lo), "f"(hi)); return d;
}
__device__ __forceinline__ u64 dup(float v) {
    u64 d; asm("mov.b64 %0,{%1,%1};" : "=l"(d) : "f"(v)); return d;
}
__device__ __forceinline__ void upk(float& lo, float& hi, u64 v) {
    asm("mov.b64 {%0,%1},%2;" : "=f"(lo), "=f"(hi) : "l"(v));
}
__device__ __forceinline__ u64 fma2(u64 a, u64 b, u64 c) {
    u64 d; asm("fma.rn.f32x2 %0,%1,%2,%3;" : "=l"(d) : "l"(a), "l"(b), "l"(c)); return d;
}
__device__ __forceinline__ u64 mul2(u64 a, u64 b) {
    u64 d; asm("mul.rn.f32x2 %0,%1,%2;" : "=l"(d) : "l"(a), "l"(b)); return d;
}
// elu on both lanes, emit each lane as a dup pair for the next layer
__device__ __forceinline__ void elu_dup(u64 s, u64& dlo, u64& dhi) {
    float lo, hi; upk(lo, hi, s);
    lo = lo > 0.0f ? lo : (__expf(lo) - 1.0f);
    hi = hi > 0.0f ? hi : (__expf(hi) - 1.0f);
    dlo = dup(lo); dhi = dup(hi);
}
// exp(0.5*x) = 2^(x * 0.72134752)
__device__ __forceinline__ float exph(float v) {
    return exp2f(v * 0.72134752044448170368f);
}
__device__ __forceinline__ void stcs2(void* p, u64 a, u64 b) {
    asm volatile("st.global.cs.v2.u64 [%0],{%1,%2};" :: "l"(p), "l"(a), "l"(b) : "memory");
}

// Shared pair layout (u64 index p), pair = (w[2jp][k], w[2jp+1][k]):
//  W1  p in [0,24):  jp=p/8 (3), k=p%8
//  W21 p in [24,36): jp=(p-24)/6 (2), k=(p-24)%6
//  W22 p in [36,48): same shape as W21
//  W3  p in [48,60): jp=(p-48)/4 (3), k=(p-48)%4
//  W4  p in [60,84): jp=(p-60)/6 (4), k=(p-60)%6
// ulonglong2 index = p/2; every (matrix, jp) row starts at an even p.

__global__ __launch_bounds__(NT)
void vae_kernel(const float4* __restrict__ x,
                const float4* __restrict__ eps,
                const float* __restrict__ w1,
                const float* __restrict__ w21,
                const float* __restrict__ w22,
                const float* __restrict__ w3,
                const float* __restrict__ w4,
                float4* __restrict__ out,
                float4* __restrict__ mu_out,
                float4* __restrict__ lv_out,
                int B)
{
    __shared__ ulonglong2 sd2[42];

    const int t  = threadIdx.x;
    const int i0 = blockIdx.x * (2 * NT) + t;
    const int i1 = i0 + NT;
    const bool v0 = i0 < B;
    const bool v1 = i1 < B;

    const float4 z4 = make_float4(0.f, 0.f, 0.f, 0.f);

    // ---- issue input loads FIRST (overlap DRAM latency with smem prologue) ----
    float4 xa0 = z4, xb0 = z4, e0 = z4, xa1 = z4, xb1 = z4, e1 = z4;
    if (v0) {
        xa0 = __ldcs(&x[2 * i0]);
        xb0 = __ldcs(&x[2 * i0 + 1]);
        e0  = __ldcs(&eps[i0]);
        if (v1) {
            xa1 = __ldcs(&x[2 * i1]);
            xb1 = __ldcs(&x[2 * i1 + 1]);
            e1  = __ldcs(&eps[i1]);
        }
    }

    // ---- stage neuron-pair weights into shared (no duplication) ----
    {
        u64* sf = (u64*)sd2;
        const int p = t;
        if (p < 84) {
            float lo, hi;
            if (p < 24) {
                const int jp = p >> 3, k = p & 7;
                lo = w1[jp * 16 + k];     hi = w1[jp * 16 + 8 + k];
            } else if (p < 36) {
                const int q = p - 24, jp = q / 6, k = q - jp * 6;
                lo = w21[jp * 12 + k];    hi = w21[jp * 12 + 6 + k];
            } else if (p < 48) {
                const int q = p - 36, jp = q / 6, k = q - jp * 6;
                lo = w22[jp * 12 + k];    hi = w22[jp * 12 + 6 + k];
            } else if (p < 60) {
                const int q = p - 48, jp = q >> 2, k = q & 3;
                lo = w3[jp * 8 + k];      hi = w3[jp * 8 + 4 + k];
            } else {
                const int q = p - 60, jp = q / 6, k = q - jp * 6;
                lo = w4[jp * 12 + k];     hi = w4[jp * 12 + 6 + k];
            }
            sf[p] = pk(lo, hi);
        }
    }
    __syncthreads();

    if (!v0) return;

    const float xs0[8] = {xa0.x, xa0.y, xa0.z, xa0.w, xb0.x, xb0.y, xb0.z, xb0.w};
    const float xs1[8] = {xa1.x, xa1.y, xa1.z, xa1.w, xb1.x, xb1.y, xb1.z, xb1.w};

    // ---- encoder: h1 = elu(x @ w1.T) as dup pairs per row ----
    u64 h1d0[6], h1d1[6];
#pragma unroll
    for (int jp = 0; jp < 3; jp++) {
        const ulonglong2 q0 = sd2[jp * 4 + 0];
        const ulonglong2 q1 = sd2[jp * 4 + 1];
        const ulonglong2 q2 = sd2[jp * 4 + 2];
        const ulonglong2 q3 = sd2[jp * 4 + 3];
        u64 s0 = mul2(dup(xs0[0]), q0.x);
        s0 = fma2(dup(xs0[1]), q0.y, s0);
        s0 = fma2(dup(xs0[2]), q1.x, s0);
        s0 = fma2(dup(xs0[3]), q1.y, s0);
        s0 = fma2(dup(xs0[4]), q2.x, s0);
        s0 = fma2(dup(xs0[5]), q2.y, s0);
        s0 = fma2(dup(xs0[6]), q3.x, s0);
        s0 = fma2(dup(xs0[7]), q3.y, s0);
        elu_dup(s0, h1d0[2 * jp], h1d0[2 * jp + 1]);
        u64 s1 = mul2(dup(xs1[0]), q0.x);
        s1 = fma2(dup(xs1[1]), q0.y, s1);
        s1 = fma2(dup(xs1[2]), q1.x, s1);
        s1 = fma2(dup(xs1[3]), q1.y, s1);
        s1 = fma2(dup(xs1[4]), q2.x, s1);
        s1 = fma2(dup(xs1[5]), q2.y, s1);
        s1 = fma2(dup(xs1[6]), q3.x, s1);
        s1 = fma2(dup(xs1[7]), q3.y, s1);
        elu_dup(s1, h1d1[2 * jp], h1d1[2 * jp + 1]);
    }

    // ---- mu / logvar (neuron pairs: jp=0 -> (mu0,mu1), jp=1 -> (mu2,mu3)) ----
    u64 mp0[2], mp1[2], lp0[2], lp1[2];
#pragma unroll
    for (int jp = 0; jp < 2; jp++) {
        const ulonglong2 m0 = sd2[12 + jp * 3 + 0];
        const ulonglong2 m1 = sd2[12 + jp * 3 + 1];
        const ulonglong2 m2 = sd2[12 + jp * 3 + 2];
        u64 a0 = mul2(h1d0[0], m0.x);
        a0 = fma2(h1d0[1], m0.y, a0);
        a0 = fma2(h1d0[2], m1.x, a0);
        a0 = fma2(h1d0[3], m1.y, a0);
        a0 = fma2(h1d0[4], m2.x, a0);
        a0 = fma2(h1d0[5], m2.y, a0);
        mp0[jp] = a0;
        u64 a1 = mul2(h1d1[0], m0.x);
        a1 = fma2(h1d1[1], m0.y, a1);
        a1 = fma2(h1d1[2], m1.x, a1);
        a1 = fma2(h1d1[3], m1.y, a1);
        a1 = fma2(h1d1[4], m2.x, a1);
        a1 = fma2(h1d1[5], m2.y, a1);
        mp1[jp] = a1;
        const ulonglong2 l0 = sd2[18 + jp * 3 + 0];
        const ulonglong2 l1 = sd2[18 + jp * 3 + 1];
        const ulonglong2 l2 = sd2[18 + jp * 3 + 2];
        u64 b0 = mul2(h1d0[0], l0.x);
        b0 = fma2(h1d0[1], l0.y, b0);
        b0 = fma2(h1d0[2], l1.x, b0);
        b0 = fma2(h1d0[3], l1.y, b0);
        b0 = fma2(h1d0[4], l2.x, b0);
        b0 = fma2(h1d0[5], l2.y, b0);
        lp0[jp] = b0;
        u64 b1 = mul2(h1d1[0], l0.x);
        b1 = fma2(h1d1[1], l0.y, b1);
        b1 = fma2(h1d1[2], l1.x, b1);
        b1 = fma2(h1d1[3], l1.y, b1);
        b1 = fma2(h1d1[4], l2.x, b1);
        b1 = fma2(h1d1[5], l2.y, b1);
        lp1[jp] = b1;
    }

    // ---- stores: pairs are already row-major (mu0,mu1),(mu2,mu3) ----
    stcs2(&mu_out[i0], mp0[0], mp0[1]);
    stcs2(&lv_out[i0], lp0[0], lp0[1]);
    if (v1) {
        stcs2(&mu_out[i1], mp1[0], mp1[1]);
        stcs2(&lv_out[i1], lp1[0], lp1[1]);
    }

    // ---- reparameterize: z = mu + eps * exp(0.5*lv), per row ----
    u64 zd0[4], zd1[4];
    {
        float a, b, c, d;
        upk(a, b, lp0[0]); upk(c, d, lp0[1]);
        const u64 zp0 = fma2(pk(e0.x, e0.y), pk(exph(a), exph(b)), mp0[0]);
        const u64 zp1 = fma2(pk(e0.z, e0.w), pk(exph(c), exph(d)), mp0[1]);
        float u, v, w, s;
        upk(u, v, zp0); upk(w, s, zp1);
        zd0[0] = dup(u); zd0[1] = dup(v); zd0[2] = dup(w); zd0[3] = dup(s);
    }
    {
        float a, b, c, d;
        upk(a, b, lp1[0]); upk(c, d, lp1[1]);
        const u64 zp0 = fma2(pk(e1.x, e1.y), pk(exph(a), exph(b)), mp1[0]);
        const u64 zp1 = fma2(pk(e1.z, e1.w), pk(exph(c), exph(d)), mp1[1]);
        float u, v, w, s;
        upk(u, v, zp0); upk(w, s, zp1);
        zd1[0] = dup(u); zd1[1] = dup(v); zd1[2] = dup(w); zd1[3] = dup(s);
    }

    // ---- decoder: h3 = elu(z @ w3.T) as dup pairs ----
    u64 h3d0[6], h3d1[6];
#pragma unroll
    for (int jp = 0; jp < 3; jp++) {
        const ulonglong2 q0 = sd2[24 + jp * 2 + 0];
        const ulonglong2 q1 = sd2[24 + jp * 2 + 1];
        u64 s0 = mul2(zd0[0], q0.x);
        s0 = fma2(zd0[1], q0.y, s0);
        s0 = fma2(zd0[2], q1.x, s0);
        s0 = fma2(zd0[3], q1.y, s0);
        elu_dup(s0, h3d0[2 * jp], h3d0[2 * jp + 1]);
        u64 s1 = mul2(zd1[0], q0.x);
        s1 = fma2(zd1[1], q0.y, s1);
        s1 = fma2(zd1[2], q1.x, s1);
        s1 = fma2(zd1[3], q1.y, s1);
        elu_dup(s1, h3d1[2 * jp], h3d1[2 * jp + 1]);
    }

    // ---- out = h3 @ w4.T (4 neuron pairs per row = full row, in order) ----
    u64 op0[4], op1[4];
#pragma unroll
    for (int jp = 0; jp < 4; jp++) {
        const ulonglong2 q0 = sd2[30 + jp * 3 + 0];
        const ulonglong2 q1 = sd2[30 + jp * 3 + 1];
        const ulonglong2 q2 = sd2[30 + jp * 3 + 2];
        u64 s0 = mul2(h3d0[0], q0.x);
        s0 = fma2(h3d0[1], q0.y, s0);
        s0 = fma2(h3d0[2], q1.x, s0);
        s0 = fma2(h3d0[3], q1.y, s0);
        s0 = fma2(h3d0[4], q2.x, s0);
        s0 = fma2(h3d0[5], q2.y, s0);
        op0[jp] = s0;
        u64 s1 = mul2(h3d1[0], q0.x);
        s1 = fma2(h3d1[1], q0.y, s1);
        s1 = fma2(h3d1[2], q1.x, s1);
        s1 = fma2(h3d1[3], q1.y, s1);
        s1 = fma2(h3d1[4], q2.x, s1);
        s1 = fma2(h3d1[5], q2.y, s1);
        op1[jp] = s1;
    }

    stcs2(&out[2 * i0],     op0[0], op0[1]);
    stcs2(&out[2 * i0 + 1], op0[2], op0[3]);
    if (v1) {
        stcs2(&out[2 * i1],     op1[0], op1[1]);
        stcs2(&out[2 * i1 + 1], op1[2], op1[3]);
    }
}

extern "C" void kernel_launch(void* const* d_in, const int* in_sizes, int n_in,
                              void* d_out, int out_size)
{
    const float4* x   = (const float4*)d_in[0];
    const float4* eps = (const float4*)d_in[1];
    const float*  w1  = (const float*)d_in[2];
    const float*  w21 = (const float*)d_in[3];
    const float*  w22 = (const float*)d_in[4];
    const float*  w3  = (const float*)d_in[5];
    const float*  w4  = (const float*)d_in[6];

    const int B = in_sizes[0] / 8;

    float* outf = (float*)d_out;
    float4* out    = (float4*)outf;
    float4* mu_out = (float4*)(outf + (size_t)B * 8);
    float4* lv_out = (float4*)(outf + (size_t)B * 12);

    const int rows_per_block = 2 * NT;
    const int grid = (B + rows_per_block - 1) / rows_per_block;
    vae_kernel<<<grid, NT>>>(x, eps, w1, w21, w22, w3, w4,
                             out, mu_out, lv_out, B);
}